// round 14
// baseline (speedup 1.0000x reference)
#include <cuda_runtime.h>

#define Dm 2048
#define Hh 16
#define Mm 8
#define Ss 8
#define Ee 8
#define KK 3
#define NTOK 64

// ---------------- scratch (device globals; no allocation allowed) ----------------
__device__ float g_x[NTOK * Dm];
__device__ float g_comb[Mm * 2 * Dm];
__device__ float g_h1[Mm * Dm];
__device__ float g_h2[Mm * (Dm / 2)];
__device__ float g_rw[Mm];
__device__ float g_mask0[Ss];
__device__ float g_q[Mm * Dm];                 // q at seq pos 0 only (bias included)
__device__ float g_u[Mm * Hh * Dm];            // u[m,h,:] = q[m,h,:]^T W_k[h-block,:]
__device__ float g_attnw[Mm * Hh * Ss];        // softmax attention weights, query 0
__device__ float g_xb[Hh * Dm];                // per-head attn-weighted mean of x
__device__ float g_abar[Dm];
__device__ float g_attended[Dm];
__device__ float g_g1[Dm / 2];
__device__ int   g_topi[KK];
__device__ float g_gates[KK];
__device__ float g_hh[KK * 2 * Dm];
__device__ float g_y[KK * Dm];

// ---------------- kernel 1: x = feats + mod_emb; summ; comb ----------------
__global__ void k_prep(const float* __restrict__ feats,
                       const float* __restrict__ mod_emb,
                       const float* __restrict__ context)
{
    int d = blockIdx.x * 256 + threadIdx.x;
    int m = blockIdx.y;
    float me = mod_emb[m * Dm + d];
    float s = 0.f;
#pragma unroll
    for (int sq = 0; sq < Ss; sq++) {
        float v = feats[(m * Ss + sq) * Dm + d] + me;
        g_x[(m * Ss + sq) * Dm + d] = v;
        s += v;
    }
    g_comb[m * 2 * Dm + d]      = s * (1.0f / Ss);
    g_comb[m * 2 * Dm + Dm + d] = context[d];
}

// ---------------- generic GEMV: C[m,j] = act(sum_i A[m,i]*B[j,i] + bias[j]) ----------------
// Weight rows (B) are single-use: stream with .cs to keep L2 for reused operands.
template <int MA, int ACT>
__global__ void k_gemv(const float* __restrict__ A, int lda,
                       const float* __restrict__ B, const float* __restrict__ bias,
                       float* __restrict__ C, int ldc, int N, int Kd)
{
    int w = threadIdx.x >> 5, lane = threadIdx.x & 31;
    int j = blockIdx.x * 8 + w;
    if (j >= N) return;
    const float4* Br = (const float4*)(B + (size_t)j * Kd);
    float acc[MA];
#pragma unroll
    for (int m = 0; m < MA; m++) acc[m] = 0.f;
    int nk = Kd >> 2;
#pragma unroll 2
    for (int i = lane; i < nk; i += 32) {
        float4 b = __ldcs(Br + i);
#pragma unroll
        for (int m = 0; m < MA; m++) {
            float4 a = __ldg((const float4*)(A + (size_t)m * lda) + i);
            acc[m] += a.x * b.x + a.y * b.y + a.z * b.z + a.w * b.w;
        }
    }
#pragma unroll
    for (int m = 0; m < MA; m++) {
#pragma unroll
        for (int off = 16; off; off >>= 1)
            acc[m] += __shfl_down_sync(0xffffffffu, acc[m], off);
    }
    if (lane == 0) {
#pragma unroll
        for (int m = 0; m < MA; m++) {
            float v = acc[m] + bias[j];
            if (ACT == 1) v = fmaxf(v, 0.f);
            C[(size_t)m * ldc + j] = v;
        }
    }
}

// ---------------- routing head: rW3 dot, sigmoid, normalize, quantile, mask row 0 ----------------
__global__ void k_routing_final(const float* __restrict__ rW3, const float* __restrict__ rb3)
{
    __shared__ float zz[8];
    __shared__ float rr[8];
    __shared__ float wv[64];
    __shared__ float tl[2];
    int tid = threadIdx.x;
    int w = tid >> 5, lane = tid & 31;
    if (w < 8) {
        const float4* a = (const float4*)(g_h2 + w * (Dm / 2));
        const float4* b = (const float4*)rW3;
        float acc = 0.f;
#pragma unroll
        for (int i = lane; i < (Dm / 2) / 4; i += 32) {
            float4 x = a[i], y = b[i];
            acc += x.x * y.x + x.y * y.y + x.z * y.z + x.w * y.w;
        }
#pragma unroll
        for (int off = 16; off; off >>= 1) acc += __shfl_down_sync(0xffffffffu, acc, off);
        if (lane == 0) zz[w] = acc;
    }
    __syncthreads();
    if (tid == 0) {
        float tot = 0.f;
        float r[8];
#pragma unroll
        for (int m = 0; m < 8; m++) {
            r[m] = 1.0f / (1.0f + expf(-(zz[m] + rb3[0])));
            tot += r[m];
        }
#pragma unroll
        for (int m = 0; m < 8; m++) {
            r[m] /= tot;
            rr[m] = r[m];
            g_rw[m] = r[m];
        }
    }
    __syncthreads();
    if (tid < 64) wv[tid] = rr[tid >> 3] * rr[tid & 7];
    __syncthreads();
    if (tid < 64) {
        float v = wv[tid];
        int rank = 0;
        for (int j = 0; j < 64; j++) {
            float o = wv[j];
            if (o < v || (o == v && j < tid)) rank++;
        }
        if (rank == 56) tl[0] = v;
        if (rank == 57) tl[1] = v;
    }
    __syncthreads();
    if (tid < 8) {
        float thr = tl[0] + 0.7f * (tl[1] - tl[0]);   // quantile(0.9): idx = 0.9*63 = 56.7
        g_mask0[tid] = (rr[0] * rr[tid] < thr) ? -1e9f : 0.0f;
    }
}

// ---------------- u[m,h,i] = sum_d q[m, h*128+d] * W_k[h*128+d, i] ----------------
// W_k = W_in rows D .. 2D.  One block per (i-chunk of 256, h).
__global__ void k_u(const float* __restrict__ Win)
{
    int h = blockIdx.y;
    int i = blockIdx.x * 256 + threadIdx.x;
    __shared__ float qs[8][128];
    for (int t = threadIdx.x; t < 1024; t += 256)
        qs[t >> 7][t & 127] = g_q[(t >> 7) * Dm + h * 128 + (t & 127)];
    __syncthreads();
    const float* Wk = Win + (size_t)Dm * Dm + (size_t)h * 128 * Dm + i;
    float acc[8];
#pragma unroll
    for (int m = 0; m < 8; m++) acc[m] = 0.f;
#pragma unroll 8
    for (int d = 0; d < 128; d++) {
        float wv = __ldcs(Wk + (size_t)d * Dm);
#pragma unroll
        for (int m = 0; m < 8; m++) acc[m] += qs[m][d] * wv;
    }
#pragma unroll
    for (int m = 0; m < 8; m++)
        g_u[(size_t)(m * Hh + h) * Dm + i] = acc[m];
}

// ---------------- scores + softmax (query 0): attn[m,h,s] ----------------
// score[m,h,s] = (u[m,h] . x[m,s]) * scale + mask0[s]   (q.b_k term cancels in softmax)
__global__ void k_scores()
{
    int m = blockIdx.x >> 4;
    int h = blockIdx.x & 15;
    int w = threadIdx.x >> 5, lane = threadIdx.x & 31;   // w = s
    __shared__ float sc[8];
    const float4* U = (const float4*)(g_u + (size_t)(m * Hh + h) * Dm);
    const float4* X = (const float4*)(g_x + (size_t)(m * 8 + w) * Dm);
    float acc = 0.f;
#pragma unroll 4
    for (int i = lane; i < Dm / 4; i += 32) {
        float4 u = U[i], x = X[i];
        acc += u.x * x.x + u.y * x.y + u.z * x.z + u.w * x.w;
    }
#pragma unroll
    for (int off = 16; off; off >>= 1) acc += __shfl_down_sync(0xffffffffu, acc, off);
    if (lane == 0) sc[w] = acc * 0.08838834764831845f + g_mask0[w];
    __syncthreads();
    if (threadIdx.x == 0) {
        float mx = -1e30f;
#pragma unroll
        for (int s = 0; s < 8; s++) mx = fmaxf(mx, sc[s]);
        float e[8];
        float den = 0.f;
#pragma unroll
        for (int s = 0; s < 8; s++) { e[s] = expf(sc[s] - mx); den += e[s]; }
        float inv = 1.0f / den;
#pragma unroll
        for (int s = 0; s < 8; s++) g_attnw[(m * Hh + h) * 8 + s] = e[s] * inv;
    }
}

// ---------------- xb[h,i] = (1/8) sum_m sum_s attn[m,h,s] x[m,s,i] ----------------
__global__ void k_xb()
{
    int h = blockIdx.y;
    int i = blockIdx.x * 256 + threadIdx.x;
    __shared__ float aw[64];
    if (threadIdx.x < 64)
        aw[threadIdx.x] = g_attnw[((threadIdx.x >> 3) * Hh + h) * 8 + (threadIdx.x & 7)];
    __syncthreads();
    float acc = 0.f;
#pragma unroll 8
    for (int t = 0; t < 64; t++)
        acc += aw[t] * g_x[(size_t)t * Dm + i];
    g_xb[(size_t)h * Dm + i] = acc * 0.125f;
}

// ---------------- abar[j] = W_v[j] . xb[h(j)] + b_v[j] ----------------
__global__ void k_abar2(const float* __restrict__ Win, const float* __restrict__ b_in)
{
    int w = threadIdx.x >> 5, lane = threadIdx.x & 31;
    int j = blockIdx.x * 8 + w;   // 0..2047
    const float4* Br = (const float4*)(Win + ((size_t)2 * Dm + j) * Dm);
    const float4* A = (const float4*)(g_xb + (size_t)(j >> 7) * Dm);
    float acc = 0.f;
#pragma unroll 4
    for (int i = lane; i < Dm / 4; i += 32) {
        float4 b = __ldcs(Br + i);
        float4 a = __ldg(A + i);
        acc += a.x * b.x + a.y * b.y + a.z * b.z + a.w * b.w;
    }
#pragma unroll
    for (int off = 16; off; off >>= 1) acc += __shfl_down_sync(0xffffffffu, acc, off);
    if (lane == 0) g_abar[j] = acc + b_in[2 * Dm + j];
}

// ---------------- gating head: logits, softmax, top-3, renorm ----------------
__global__ void k_gate2(const float* __restrict__ gW2, const float* __restrict__ gb2)
{
    __shared__ float logits[8];
    int w = threadIdx.x >> 5, lane = threadIdx.x & 31;
    const float4* Br = (const float4*)(gW2 + (size_t)w * (Dm / 2));
    const float4* A = (const float4*)g_g1;
    float acc = 0.f;
#pragma unroll
    for (int i = lane; i < (Dm / 2) / 4; i += 32) {
        float4 b = Br[i], a = A[i];
        acc += a.x * b.x + a.y * b.y + a.z * b.z + a.w * b.w;
    }
#pragma unroll
    for (int off = 16; off; off >>= 1) acc += __shfl_down_sync(0xffffffffu, acc, off);
    if (lane == 0) logits[w] = acc + gb2[w];
    __syncthreads();
    if (threadIdx.x == 0) {
        float mx = -1e30f;
#pragma unroll
        for (int e = 0; e < 8; e++) mx = fmaxf(mx, logits[e]);
        float p[8];
        float den = 0.f;
#pragma unroll
        for (int e = 0; e < 8; e++) { p[e] = expf(logits[e] - mx); den += p[e]; }
#pragma unroll
        for (int e = 0; e < 8; e++) p[e] /= den;
        bool used[8] = {false, false, false, false, false, false, false, false};
        int ti[KK]; float tv[KK];
        for (int k = 0; k < KK; k++) {
            int b = -1; float bv = -1e30f;
            for (int e = 0; e < 8; e++)
                if (!used[e] && p[e] > bv) { bv = p[e]; b = e; }
            used[b] = true; ti[k] = b; tv[k] = bv;
        }
        float m2 = tv[0];
        float ex[KK]; float d2 = 0.f;
        for (int k = 0; k < KK; k++) { ex[k] = expf(tv[k] - m2); d2 += ex[k]; }
        for (int k = 0; k < KK; k++) { g_gates[k] = ex[k] / d2; g_topi[k] = ti[k]; }
    }
}

// ---------------- expert FC1 (gelu) and FC2, indexed by g_topi ----------------
__global__ void k_expert_fc1(const float* __restrict__ eW1, const float* __restrict__ eb1)
{
    int slot = blockIdx.y;
    int e = g_topi[slot];
    int w = threadIdx.x >> 5, lane = threadIdx.x & 31;
    int j = blockIdx.x * 8 + w;   // 0..4095
    const float4* Br = (const float4*)(eW1 + ((size_t)e * 2 * Dm + j) * Dm);
    const float4* A = (const float4*)g_attended;
    float acc = 0.f;
#pragma unroll 4
    for (int i = lane; i < Dm / 4; i += 32) {
        float4 b = __ldcs(Br + i);
        float4 a = __ldg(A + i);
        acc += a.x * b.x + a.y * b.y + a.z * b.z + a.w * b.w;
    }
#pragma unroll
    for (int off = 16; off; off >>= 1) acc += __shfl_down_sync(0xffffffffu, acc, off);
    if (lane == 0) {
        float v = acc + eb1[(size_t)e * 2 * Dm + j];
        g_hh[slot * 2 * Dm + j] = 0.5f * v * (1.0f + erff(v * 0.70710678118654752f));
    }
}

__global__ void k_expert_fc2(const float* __restrict__ eW2, const float* __restrict__ eb2)
{
    int slot = blockIdx.y;
    int e = g_topi[slot];
    int w = threadIdx.x >> 5, lane = threadIdx.x & 31;
    int j = blockIdx.x * 8 + w;   // 0..2047
    const float4* Br = (const float4*)(eW2 + ((size_t)e * Dm + j) * 2 * Dm);
    const float4* A = (const float4*)(g_hh + slot * 2 * Dm);
    float acc = 0.f;
#pragma unroll 4
    for (int i = lane; i < (2 * Dm) / 4; i += 32) {
        float4 b = __ldcs(Br + i);
        float4 a = __ldg(A + i);
        acc += a.x * b.x + a.y * b.y + a.z * b.z + a.w * b.w;
    }
#pragma unroll
    for (int off = 16; off; off >>= 1) acc += __shfl_down_sync(0xffffffffu, acc, off);
    if (lane == 0)
        g_y[slot * Dm + j] = acc + eb2[(size_t)e * Dm + j];
}

// ---------------- per-expert LayerNorm + gated combine + write rw ----------------
__device__ __forceinline__ float blkred256(float v)
{
    __shared__ float sh[8];
    int lane = threadIdx.x & 31, w = threadIdx.x >> 5;
#pragma unroll
    for (int off = 16; off; off >>= 1) v += __shfl_down_sync(0xffffffffu, v, off);
    if (lane == 0) sh[w] = v;
    __syncthreads();
    float tot;
    if (threadIdx.x == 0) {
        tot = 0.f;
#pragma unroll
        for (int i = 0; i < 8; i++) tot += sh[i];
        sh[0] = tot;
    }
    __syncthreads();
    tot = sh[0];
    __syncthreads();
    return tot;
}

__global__ void k_final(const float* __restrict__ e_gamma, const float* __restrict__ e_beta,
                        float* __restrict__ out)
{
    int tid = threadIdx.x;
    float fused[8];
#pragma unroll
    for (int r = 0; r < 8; r++) fused[r] = 0.f;
    for (int slot = 0; slot < KK; slot++) {
        int e = g_topi[slot];
        float gate = g_gates[slot];
        float yv[8];
        float s = 0.f;
#pragma unroll
        for (int r = 0; r < 8; r++) { yv[r] = g_y[slot * Dm + tid + r * 256]; s += yv[r]; }
        float mu = blkred256(s) * (1.0f / Dm);
        float v = 0.f;
#pragma unroll
        for (int r = 0; r < 8; r++) { float d = yv[r] - mu; v += d * d; }
        float var = blkred256(v) * (1.0f / Dm);
        float rstd = rsqrtf(var + 1e-5f);
#pragma unroll
        for (int r = 0; r < 8; r++) {
            int idx = tid + r * 256;
            fused[r] += gate * ((yv[r] - mu) * rstd * e_gamma[(size_t)e * Dm + idx]
                                + e_beta[(size_t)e * Dm + idx]);
        }
    }
#pragma unroll
    for (int r = 0; r < 8; r++) out[tid + r * 256] = fused[r];
    if (tid < Mm) out[Dm + tid] = g_rw[tid];
}

// ---------------- launch ----------------
extern "C" void kernel_launch(void* const* d_in, const int* in_sizes, int n_in,
                              void* d_out, int out_size)
{
    const float* feats   = (const float*)d_in[0];
    const float* context = (const float*)d_in[1];
    const float* mod_emb = (const float*)d_in[2];
    const float* rW1     = (const float*)d_in[3];
    const float* rb1     = (const float*)d_in[4];
    const float* rW2     = (const float*)d_in[5];
    const float* rb2     = (const float*)d_in[6];
    const float* rW3     = (const float*)d_in[7];
    const float* rb3     = (const float*)d_in[8];
    const float* W_in    = (const float*)d_in[9];
    const float* b_in    = (const float*)d_in[10];
    const float* W_out   = (const float*)d_in[11];
    const float* b_out   = (const float*)d_in[12];
    const float* gW1     = (const float*)d_in[13];
    const float* gb1     = (const float*)d_in[14];
    const float* gW2     = (const float*)d_in[15];
    const float* gb2     = (const float*)d_in[16];
    const float* eW1     = (const float*)d_in[17];
    const float* eb1     = (const float*)d_in[18];
    const float* eW2     = (const float*)d_in[19];
    const float* eb2     = (const float*)d_in[20];
    const float* e_gamma = (const float*)d_in[21];
    const float* e_beta  = (const float*)d_in[22];
    float* out = (float*)d_out;

    void *p_comb, *p_h1, *p_h2, *p_x, *p_q, *p_abar, *p_att, *p_g1;
    cudaGetSymbolAddress(&p_comb, g_comb);
    cudaGetSymbolAddress(&p_h1, g_h1);
    cudaGetSymbolAddress(&p_h2, g_h2);
    cudaGetSymbolAddress(&p_x, g_x);
    cudaGetSymbolAddress(&p_q, g_q);
    cudaGetSymbolAddress(&p_abar, g_abar);
    cudaGetSymbolAddress(&p_att, g_attended);
    cudaGetSymbolAddress(&p_g1, g_g1);

    k_prep<<<dim3(Dm / 256, Mm), 256>>>(feats, mod_emb, context);

    // q (seq position 0 of each modality; row stride S*D in g_x), then u = q^T W_k
    k_gemv<8, 0><<<Dm / 8, 256>>>((const float*)p_x, Ss * Dm, W_in, b_in, (float*)p_q, Dm, Dm, Dm);
    k_u<<<dim3(Dm / 256, Hh), 256>>>(W_in);

    // routing chain (produces mask row 0)
    k_gemv<8, 1><<<Dm / 8, 256>>>((const float*)p_comb, 2 * Dm, rW1, rb1, (float*)p_h1, Dm, Dm, 2 * Dm);
    k_gemv<8, 1><<<(Dm / 2) / 8, 256>>>((const float*)p_h1, Dm, rW2, rb2, (float*)p_h2, Dm / 2, Dm / 2, Dm);
    k_routing_final<<<1, 256>>>(rW3, rb3);

    // attention (query 0 only), fully factored
    k_scores<<<Mm * Hh, 256>>>();
    k_xb<<<dim3(Dm / 256, Hh), 256>>>();
    k_abar2<<<Dm / 8, 256>>>(W_in, b_in);

    k_gemv<1, 0><<<Dm / 8, 256>>>((const float*)p_abar, 0, W_out, b_out, (float*)p_att, Dm, Dm, Dm);
    k_gemv<1, 1><<<(Dm / 2) / 8, 256>>>((const float*)p_att, 0, gW1, gb1, (float*)p_g1, Dm / 2, Dm / 2, Dm);
    k_gate2<<<1, 256>>>(gW2, gb2);

    k_expert_fc1<<<dim3((2 * Dm) / 8, KK), 256>>>(eW1, eb1);
    k_expert_fc2<<<dim3(Dm / 8, KK), 256>>>(eW2, eb2);

    k_final<<<1, 256>>>(e_gamma, e_beta, out);
}

// round 17
// speedup vs baseline: 1.2495x; 1.2495x over previous
#include <cuda_runtime.h>

#define Dm 2048
#define Hh 16
#define Mm 8
#define Ss 8
#define Ee 8
#define KK 3
#define NTOK 64

// ---------------- scratch (device globals; no allocation allowed) ----------------
__device__ float g_x[NTOK * Dm];
__device__ float g_comb[Mm * 2 * Dm];
__device__ float g_h1[Mm * Dm];
__device__ float g_h2[Mm * (Dm / 2)];
__device__ float g_rw[Mm];
__device__ float g_mask0[Ss];
__device__ float g_q[Mm * Dm];                 // q at seq pos 0 only (bias included)
__device__ float g_u[Mm * Hh * Dm];            // u[m,h,:] = q[m,h,:]^T W_k[h-block,:]
__device__ float g_attnw[Mm * Hh * Ss];        // softmax attention weights, query 0
__device__ float g_xb[Hh * Dm];                // per-head attn-weighted mean of x
__device__ float g_abar[Dm];
__device__ float g_attended[Dm];
__device__ float g_g1[Dm / 2];
__device__ int   g_topi[KK];
__device__ float g_gates[KK];
__device__ float g_hh[KK * 2 * Dm];
__device__ float g_y[KK * Dm];

// ---------------- kernel 1: x = feats + mod_emb; summ; comb ----------------
__global__ void k_prep(const float* __restrict__ feats,
                       const float* __restrict__ mod_emb,
                       const float* __restrict__ context)
{
    int d = blockIdx.x * 256 + threadIdx.x;
    int m = blockIdx.y;
    float me = mod_emb[m * Dm + d];
    float s = 0.f;
#pragma unroll
    for (int sq = 0; sq < Ss; sq++) {
        float v = feats[(m * Ss + sq) * Dm + d] + me;
        g_x[(m * Ss + sq) * Dm + d] = v;
        s += v;
    }
    g_comb[m * 2 * Dm + d]      = s * (1.0f / Ss);
    g_comb[m * 2 * Dm + Dm + d] = context[d];
}

// ---------------- split-K GEMV: C[m,j] = act(sum_i A[m,i]*B[j,i] + bias[j]) ----------------
// 256 threads = 8 warps; 4 warps per output (K-quarters), 2 outputs per block.
// 4x the warps of warp-per-row => occupancy + MLP fix for latency-bound GEMV.
template <int MA, int ACT>
__global__ void k_gemv2(const float* __restrict__ A, int lda,
                        const float* __restrict__ B, const float* __restrict__ bias,
                        float* __restrict__ C, int ldc, int N, int Kd)
{
    int warp = threadIdx.x >> 5, lane = threadIdx.x & 31;
    int jloc = warp >> 2;          // 0..1  output within block
    int kseg = warp & 3;           // 0..3  K quarter
    int j = blockIdx.x * 2 + jloc;
    __shared__ float red[2][4][MA];
    int nk = Kd >> 2;              // float4 count per row
    int seg = nk >> 2;             // per-warp segment
    const float4* Br = (const float4*)(B + (size_t)j * Kd) + kseg * seg;
    float acc[MA];
#pragma unroll
    for (int m = 0; m < MA; m++) acc[m] = 0.f;
#pragma unroll 4
    for (int i = lane; i < seg; i += 32) {
        float4 b = __ldcs(Br + i);
#pragma unroll
        for (int m = 0; m < MA; m++) {
            float4 a = __ldg((const float4*)(A + (size_t)m * lda) + kseg * seg + i);
            acc[m] += a.x * b.x + a.y * b.y + a.z * b.z + a.w * b.w;
        }
    }
#pragma unroll
    for (int m = 0; m < MA; m++)
#pragma unroll
        for (int off = 16; off; off >>= 1)
            acc[m] += __shfl_down_sync(0xffffffffu, acc[m], off);
    if (lane == 0)
#pragma unroll
        for (int m = 0; m < MA; m++) red[jloc][kseg][m] = acc[m];
    __syncthreads();
    if (kseg == 0 && lane == 0) {
#pragma unroll
        for (int m = 0; m < MA; m++) {
            float v = red[jloc][0][m] + red[jloc][1][m] + red[jloc][2][m]
                    + red[jloc][3][m] + bias[j];
            if (ACT == 1) v = fmaxf(v, 0.f);
            C[(size_t)m * ldc + j] = v;
        }
    }
}

// ---------------- routing head: rW3 dot, sigmoid, normalize, quantile, mask row 0 ----------------
__global__ void k_routing_final(const float* __restrict__ rW3, const float* __restrict__ rb3)
{
    __shared__ float zz[8];
    __shared__ float rr[8];
    __shared__ float wv[64];
    __shared__ float tl[2];
    int tid = threadIdx.x;
    int w = tid >> 5, lane = tid & 31;
    if (w < 8) {
        const float4* a = (const float4*)(g_h2 + w * (Dm / 2));
        const float4* b = (const float4*)rW3;
        float acc = 0.f;
#pragma unroll
        for (int i = lane; i < (Dm / 2) / 4; i += 32) {
            float4 x = a[i], y = b[i];
            acc += x.x * y.x + x.y * y.y + x.z * y.z + x.w * y.w;
        }
#pragma unroll
        for (int off = 16; off; off >>= 1) acc += __shfl_down_sync(0xffffffffu, acc, off);
        if (lane == 0) zz[w] = acc;
    }
    __syncthreads();
    if (tid == 0) {
        float tot = 0.f;
        float r[8];
#pragma unroll
        for (int m = 0; m < 8; m++) {
            r[m] = 1.0f / (1.0f + expf(-(zz[m] + rb3[0])));
            tot += r[m];
        }
#pragma unroll
        for (int m = 0; m < 8; m++) {
            r[m] /= tot;
            rr[m] = r[m];
            g_rw[m] = r[m];
        }
    }
    __syncthreads();
    if (tid < 64) wv[tid] = rr[tid >> 3] * rr[tid & 7];
    __syncthreads();
    if (tid < 64) {
        float v = wv[tid];
        int rank = 0;
        for (int j = 0; j < 64; j++) {
            float o = wv[j];
            if (o < v || (o == v && j < tid)) rank++;
        }
        if (rank == 56) tl[0] = v;
        if (rank == 57) tl[1] = v;
    }
    __syncthreads();
    if (tid < 8) {
        float thr = tl[0] + 0.7f * (tl[1] - tl[0]);   // quantile(0.9): idx = 0.9*63 = 56.7
        g_mask0[tid] = (rr[0] * rr[tid] < thr) ? -1e9f : 0.0f;
    }
}

// ---------------- u[m,h,i] = sum_d q[m, h*128+d] * W_k[h*128+d, i] ----------------
// W_k = W_in rows D .. 2D.  One block per (i-chunk of 256, h).
__global__ void k_u(const float* __restrict__ Win)
{
    int h = blockIdx.y;
    int i = blockIdx.x * 256 + threadIdx.x;
    __shared__ float qs[8][128];
    for (int t = threadIdx.x; t < 1024; t += 256)
        qs[t >> 7][t & 127] = g_q[(t >> 7) * Dm + h * 128 + (t & 127)];
    __syncthreads();
    const float* Wk = Win + (size_t)Dm * Dm + (size_t)h * 128 * Dm + i;
    float acc[8];
#pragma unroll
    for (int m = 0; m < 8; m++) acc[m] = 0.f;
#pragma unroll 16
    for (int d = 0; d < 128; d++) {
        float wv = __ldcs(Wk + (size_t)d * Dm);
#pragma unroll
        for (int m = 0; m < 8; m++) acc[m] += qs[m][d] * wv;
    }
#pragma unroll
    for (int m = 0; m < 8; m++)
        g_u[(size_t)(m * Hh + h) * Dm + i] = acc[m];
}

// ---------------- scores + softmax (query 0): attn[m,h,s] ----------------
// score[m,h,s] = (u[m,h] . x[m,s]) * scale + mask0[s]   (q.b_k term cancels in softmax)
__global__ void k_scores()
{
    int m = blockIdx.x >> 4;
    int h = blockIdx.x & 15;
    int w = threadIdx.x >> 5, lane = threadIdx.x & 31;   // w = s
    __shared__ float sc[8];
    const float4* U = (const float4*)(g_u + (size_t)(m * Hh + h) * Dm);
    const float4* X = (const float4*)(g_x + (size_t)(m * 8 + w) * Dm);
    float acc = 0.f;
#pragma unroll 4
    for (int i = lane; i < Dm / 4; i += 32) {
        float4 u = U[i], x = X[i];
        acc += u.x * x.x + u.y * x.y + u.z * x.z + u.w * x.w;
    }
#pragma unroll
    for (int off = 16; off; off >>= 1) acc += __shfl_down_sync(0xffffffffu, acc, off);
    if (lane == 0) sc[w] = acc * 0.08838834764831845f + g_mask0[w];
    __syncthreads();
    if (threadIdx.x == 0) {
        float mx = -1e30f;
#pragma unroll
        for (int s = 0; s < 8; s++) mx = fmaxf(mx, sc[s]);
        float e[8];
        float den = 0.f;
#pragma unroll
        for (int s = 0; s < 8; s++) { e[s] = expf(sc[s] - mx); den += e[s]; }
        float inv = 1.0f / den;
#pragma unroll
        for (int s = 0; s < 8; s++) g_attnw[(m * Hh + h) * 8 + s] = e[s] * inv;
    }
}

// ---------------- xb[h,i] = (1/8) sum_m sum_s attn[m,h,s] x[m,s,i] ----------------
__global__ void k_xb()
{
    int h = blockIdx.y;
    int i = blockIdx.x * 256 + threadIdx.x;
    __shared__ float aw[64];
    if (threadIdx.x < 64)
        aw[threadIdx.x] = g_attnw[((threadIdx.x >> 3) * Hh + h) * 8 + (threadIdx.x & 7)];
    __syncthreads();
    float acc = 0.f;
#pragma unroll 8
    for (int t = 0; t < 64; t++)
        acc += aw[t] * g_x[(size_t)t * Dm + i];
    g_xb[(size_t)h * Dm + i] = acc * 0.125f;
}

// ---------------- abar[j] = W_v[j] . xb[h(j)] + b_v[j]  (split-K x4) ----------------
__global__ void k_abar2(const float* __restrict__ Win, const float* __restrict__ b_in)
{
    int warp = threadIdx.x >> 5, lane = threadIdx.x & 31;
    int jloc = warp >> 2;
    int kseg = warp & 3;
    int j = blockIdx.x * 2 + jloc;   // 0..2047
    __shared__ float red[2][4];
    const int seg = (Dm / 4) / 4;    // 128 float4s per quarter
    const float4* Br = (const float4*)(Win + ((size_t)2 * Dm + j) * Dm) + kseg * seg;
    const float4* A = (const float4*)(g_xb + (size_t)(j >> 7) * Dm) + kseg * seg;
    float acc = 0.f;
#pragma unroll 4
    for (int i = lane; i < seg; i += 32) {
        float4 b = __ldcs(Br + i);
        float4 a = __ldg(A + i);
        acc += a.x * b.x + a.y * b.y + a.z * b.z + a.w * b.w;
    }
#pragma unroll
    for (int off = 16; off; off >>= 1) acc += __shfl_down_sync(0xffffffffu, acc, off);
    if (lane == 0) red[jloc][kseg] = acc;
    __syncthreads();
    if (kseg == 0 && lane == 0)
        g_abar[j] = red[jloc][0] + red[jloc][1] + red[jloc][2] + red[jloc][3]
                  + b_in[2 * Dm + j];
}

// ---------------- gating head: logits, softmax, top-3, renorm ----------------
__global__ void k_gate2(const float* __restrict__ gW2, const float* __restrict__ gb2)
{
    __shared__ float logits[8];
    int w = threadIdx.x >> 5, lane = threadIdx.x & 31;
    const float4* Br = (const float4*)(gW2 + (size_t)w * (Dm / 2));
    const float4* A = (const float4*)g_g1;
    float acc = 0.f;
#pragma unroll
    for (int i = lane; i < (Dm / 2) / 4; i += 32) {
        float4 b = Br[i], a = A[i];
        acc += a.x * b.x + a.y * b.y + a.z * b.z + a.w * b.w;
    }
#pragma unroll
    for (int off = 16; off; off >>= 1) acc += __shfl_down_sync(0xffffffffu, acc, off);
    if (lane == 0) logits[w] = acc + gb2[w];
    __syncthreads();
    if (threadIdx.x == 0) {
        float mx = -1e30f;
#pragma unroll
        for (int e = 0; e < 8; e++) mx = fmaxf(mx, logits[e]);
        float p[8];
        float den = 0.f;
#pragma unroll
        for (int e = 0; e < 8; e++) { p[e] = expf(logits[e] - mx); den += p[e]; }
#pragma unroll
        for (int e = 0; e < 8; e++) p[e] /= den;
        bool used[8] = {false, false, false, false, false, false, false, false};
        int ti[KK]; float tv[KK];
        for (int k = 0; k < KK; k++) {
            int b = -1; float bv = -1e30f;
            for (int e = 0; e < 8; e++)
                if (!used[e] && p[e] > bv) { bv = p[e]; b = e; }
            used[b] = true; ti[k] = b; tv[k] = bv;
        }
        float m2 = tv[0];
        float ex[KK]; float d2 = 0.f;
        for (int k = 0; k < KK; k++) { ex[k] = expf(tv[k] - m2); d2 += ex[k]; }
        for (int k = 0; k < KK; k++) { g_gates[k] = ex[k] / d2; g_topi[k] = ti[k]; }
    }
}

// ---------------- expert FC1 (gelu) and FC2, indexed by g_topi ----------------
// Dual-stride loads + 2 accumulators: 4+ independent loads in flight per warp.
__global__ void k_expert_fc1(const float* __restrict__ eW1, const float* __restrict__ eb1)
{
    int slot = blockIdx.y;
    int e = g_topi[slot];
    int w = threadIdx.x >> 5, lane = threadIdx.x & 31;
    int j = blockIdx.x * 8 + w;   // 0..4095
    const float4* Br = (const float4*)(eW1 + ((size_t)e * 2 * Dm + j) * Dm);
    const float4* A = (const float4*)g_attended;
    float acc0 = 0.f, acc1 = 0.f;
    const int nk = Dm / 4;        // 512
#pragma unroll 4
    for (int i = lane; i < nk; i += 64) {
        float4 b0 = __ldcs(Br + i);
        float4 b1 = __ldcs(Br + i + 32);
        float4 a0 = __ldg(A + i);
        float4 a1 = __ldg(A + i + 32);
        acc0 += a0.x * b0.x + a0.y * b0.y + a0.z * b0.z + a0.w * b0.w;
        acc1 += a1.x * b1.x + a1.y * b1.y + a1.z * b1.z + a1.w * b1.w;
    }
    float acc = acc0 + acc1;
#pragma unroll
    for (int off = 16; off; off >>= 1) acc += __shfl_down_sync(0xffffffffu, acc, off);
    if (lane == 0) {
        float v = acc + eb1[(size_t)e * 2 * Dm + j];
        g_hh[slot * 2 * Dm + j] = 0.5f * v * (1.0f + erff(v * 0.70710678118654752f));
    }
}

__global__ void k_expert_fc2(const float* __restrict__ eW2, const float* __restrict__ eb2)
{
    int slot = blockIdx.y;
    int e = g_topi[slot];
    int w = threadIdx.x >> 5, lane = threadIdx.x & 31;
    int j = blockIdx.x * 8 + w;   // 0..2047
    const float4* Br = (const float4*)(eW2 + ((size_t)e * Dm + j) * 2 * Dm);
    const float4* A = (const float4*)(g_hh + slot * 2 * Dm);
    float acc0 = 0.f, acc1 = 0.f;
    const int nk = (2 * Dm) / 4;  // 1024
#pragma unroll 4
    for (int i = lane; i < nk; i += 64) {
        float4 b0 = __ldcs(Br + i);
        float4 b1 = __ldcs(Br + i + 32);
        float4 a0 = __ldg(A + i);
        float4 a1 = __ldg(A + i + 32);
        acc0 += a0.x * b0.x + a0.y * b0.y + a0.z * b0.z + a0.w * b0.w;
        acc1 += a1.x * b1.x + a1.y * b1.y + a1.z * b1.z + a1.w * b1.w;
    }
    float acc = acc0 + acc1;
#pragma unroll
    for (int off = 16; off; off >>= 1) acc += __shfl_down_sync(0xffffffffu, acc, off);
    if (lane == 0)
        g_y[slot * Dm + j] = acc + eb2[(size_t)e * Dm + j];
}

// ---------------- per-expert LayerNorm + gated combine + write rw ----------------
__device__ __forceinline__ float blkred256(float v)
{
    __shared__ float sh[8];
    int lane = threadIdx.x & 31, w = threadIdx.x >> 5;
#pragma unroll
    for (int off = 16; off; off >>= 1) v += __shfl_down_sync(0xffffffffu, v, off);
    if (lane == 0) sh[w] = v;
    __syncthreads();
    float tot;
    if (threadIdx.x == 0) {
        tot = 0.f;
#pragma unroll
        for (int i = 0; i < 8; i++) tot += sh[i];
        sh[0] = tot;
    }
    __syncthreads();
    tot = sh[0];
    __syncthreads();
    return tot;
}

__global__ void k_final(const float* __restrict__ e_gamma, const float* __restrict__ e_beta,
                        float* __restrict__ out)
{
    int tid = threadIdx.x;
    float fused[8];
#pragma unroll
    for (int r = 0; r < 8; r++) fused[r] = 0.f;
    for (int slot = 0; slot < KK; slot++) {
        int e = g_topi[slot];
        float gate = g_gates[slot];
        float yv[8];
        float s = 0.f;
#pragma unroll
        for (int r = 0; r < 8; r++) { yv[r] = g_y[slot * Dm + tid + r * 256]; s += yv[r]; }
        float mu = blkred256(s) * (1.0f / Dm);
        float v = 0.f;
#pragma unroll
        for (int r = 0; r < 8; r++) { float d = yv[r] - mu; v += d * d; }
        float var = blkred256(v) * (1.0f / Dm);
        float rstd = rsqrtf(var + 1e-5f);
#pragma unroll
        for (int r = 0; r < 8; r++) {
            int idx = tid + r * 256;
            fused[r] += gate * ((yv[r] - mu) * rstd * e_gamma[(size_t)e * Dm + idx]
                                + e_beta[(size_t)e * Dm + idx]);
        }
    }
#pragma unroll
    for (int r = 0; r < 8; r++) out[tid + r * 256] = fused[r];
    if (tid < Mm) out[Dm + tid] = g_rw[tid];
}

// ---------------- launch ----------------
extern "C" void kernel_launch(void* const* d_in, const int* in_sizes, int n_in,
                              void* d_out, int out_size)
{
    const float* feats   = (const float*)d_in[0];
    const float* context = (const float*)d_in[1];
    const float* mod_emb = (const float*)d_in[2];
    const float* rW1     = (const float*)d_in[3];
    const float* rb1     = (const float*)d_in[4];
    const float* rW2     = (const float*)d_in[5];
    const float* rb2     = (const float*)d_in[6];
    const float* rW3     = (const float*)d_in[7];
    const float* rb3     = (const float*)d_in[8];
    const float* W_in    = (const float*)d_in[9];
    const float* b_in    = (const float*)d_in[10];
    const float* W_out   = (const float*)d_in[11];
    const float* b_out   = (const float*)d_in[12];
    const float* gW1     = (const float*)d_in[13];
    const float* gb1     = (const float*)d_in[14];
    const float* gW2     = (const float*)d_in[15];
    const float* gb2     = (const float*)d_in[16];
    const float* eW1     = (const float*)d_in[17];
    const float* eb1     = (const float*)d_in[18];
    const float* eW2     = (const float*)d_in[19];
    const float* eb2     = (const float*)d_in[20];
    const float* e_gamma = (const float*)d_in[21];
    const float* e_beta  = (const float*)d_in[22];
    float* out = (float*)d_out;

    void *p_comb, *p_h1, *p_h2, *p_x, *p_q, *p_abar, *p_att, *p_g1;
    cudaGetSymbolAddress(&p_comb, g_comb);
    cudaGetSymbolAddress(&p_h1, g_h1);
    cudaGetSymbolAddress(&p_h2, g_h2);
    cudaGetSymbolAddress(&p_x, g_x);
    cudaGetSymbolAddress(&p_q, g_q);
    cudaGetSymbolAddress(&p_abar, g_abar);
    cudaGetSymbolAddress(&p_att, g_attended);
    cudaGetSymbolAddress(&p_g1, g_g1);

    k_prep<<<dim3(Dm / 256, Mm), 256>>>(feats, mod_emb, context);

    // q (seq position 0 of each modality; row stride S*D in g_x), then u = q^T W_k
    k_gemv2<8, 0><<<Dm / 2, 256>>>((const float*)p_x, Ss * Dm, W_in, b_in, (float*)p_q, Dm, Dm, Dm);
    k_u<<<dim3(Dm / 256, Hh), 256>>>(W_in);

    // routing chain (produces mask row 0)
    k_gemv2<8, 1><<<Dm / 2, 256>>>((const float*)p_comb, 2 * Dm, rW1, rb1, (float*)p_h1, Dm, Dm, 2 * Dm);
    k_gemv2<8, 1><<<(Dm / 2) / 2, 256>>>((const float*)p_h1, Dm, rW2, rb2, (float*)p_h2, Dm / 2, Dm / 2, Dm);
    k_routing_final<<<1, 256>>>(rW3, rb3);

    // attention (query 0 only), fully factored
    k_scores<<<Mm * Hh, 256>>>();
    k_xb<<<dim3(Dm / 256, Hh), 256>>>();
    k_abar2<<<Dm / 2, 256>>>(W_in, b_in);

    k_gemv2<1, 0><<<Dm / 2, 256>>>((const float*)p_abar, 0, W_out, b_out, (float*)p_att, Dm, Dm, Dm);
    k_gemv2<1, 1><<<(Dm / 2) / 2, 256>>>((const float*)p_att, 0, gW1, gb1, (float*)p_g1, Dm / 2, Dm / 2, Dm);
    k_gate2<<<1, 256>>>(gW2, gb2);

    k_expert_fc1<<<dim3((2 * Dm) / 8, KK), 256>>>(eW1, eb1);
    k_expert_fc2<<<dim3(Dm / 8, KK), 256>>>(eW2, eb2);

    k_final<<<1, 256>>>(e_gamma, e_beta, out);
}